// round 2
// baseline (speedup 1.0000x reference)
#include <cuda_runtime.h>

// Problem constants
#define DD   128   // feature dim
#define CO   16    // output channels
#define PPV  16    // P*P
#define HG   32    // sqrt(N)
#define NB   32    // batch

// ---------------------------------------------------------------------------
// Fused kernel: one block per (hg, b). 256 threads.
//   Phase 0 : cooperative smem loads: x tile (32x128), W (16x128 padded),
//             emb[0:16] (16x128 padded), mask row.
//   Phase 1a: xW[wg][p] = x[b, hg*32+wg] . W[p]        (512 dots, 2 per thread)
//   Phase 1b: cb[c][p]  = emb[c] . W[p] + bias[p]      (256 dots, 1 per thread)
//   Phase 2 : out[b,c,hg*4+pr, wg*4+pc] = (xW + cb) * mask[b][c]
//             One warp-wide STG.128 row per (c,pr): 512B contiguous, coalesced.
// ---------------------------------------------------------------------------
__global__ void __launch_bounds__(256, 1)
decoder_kernel(const float* __restrict__ x,
               const float* __restrict__ W,
               const float* __restrict__ emb,
               const float* __restrict__ bias,
               const float* __restrict__ mask,
               float* __restrict__ out) {
    __shared__ float xs[HG * DD];        // 32 x 128 (quarter-warp broadcast reads)
    __shared__ float ws[PPV * 132];      // 16 rows padded to 132 -> conflict-free LDS.128
    __shared__ float es[CO * 132];       // emb rows, same padding
    __shared__ float xw[HG * 20];        // 32 x 16 padded to 20 -> conflict-free epilogue LDS.128
    __shared__ float cbs[CO * PPV];
    __shared__ float ms[CO];

    const int t  = threadIdx.x;
    const int hg = blockIdx.x;
    const int b  = blockIdx.y;

    // ---- Phase 0: cooperative loads -------------------------------------
    {
        // x rows n = hg*32 .. hg*32+31 are contiguous: 1024 float4
        const float4* xg = reinterpret_cast<const float4*>(
            x + (size_t)(b * (HG * HG) + hg * HG) * DD);
        float4* xs4 = reinterpret_cast<float4*>(xs);
        #pragma unroll
        for (int k = 0; k < 4; k++) xs4[t + k * 256] = xg[t + k * 256];

        // W: 512 float4 -> padded rows; emb[0:16]: same shape
        const float4* wg4 = reinterpret_cast<const float4*>(W);
        const float4* eg4 = reinterpret_cast<const float4*>(emb);
        #pragma unroll
        for (int k = 0; k < 2; k++) {
            int j = t + k * 256;            // 0..511
            int p = j >> 5;                 // row
            int i = j & 31;                 // float4 within row
            *reinterpret_cast<float4*>(&ws[p * 132 + i * 4]) = wg4[j];
            *reinterpret_cast<float4*>(&es[p * 132 + i * 4]) = eg4[j];
        }

        if (t < CO)
            ms[t] = mask[b * CO + t];
    }
    __syncthreads();

    // ---- Phase 1a: xW ---------------------------------------------------
    {
        const int wg = t >> 3;              // 0..31 : which n within the tile
        const int pp = t & 7;               // computes p = pp and p = pp+8
        const float4* xr = reinterpret_cast<const float4*>(xs + wg * DD);
        float acc0 = 0.f, acc1 = 0.f;
        #pragma unroll
        for (int i = 0; i < DD / 4; i++) {
            float4 xv = xr[i];              // broadcast within quarter-warp
            float4 wa = *reinterpret_cast<const float4*>(&ws[pp * 132 + i * 4]);
            float4 wb = *reinterpret_cast<const float4*>(&ws[(pp + 8) * 132 + i * 4]);
            acc0 += xv.x * wa.x + xv.y * wa.y + xv.z * wa.z + xv.w * wa.w;
            acc1 += xv.x * wb.x + xv.y * wb.y + xv.z * wb.z + xv.w * wb.w;
        }
        xw[wg * 20 + pp]     = acc0;
        xw[wg * 20 + pp + 8] = acc1;
    }

    // ---- Phase 1b: cb[c][p] = emb[c].W[p] + bias[p] ---------------------
    {
        const int c = t >> 4;               // 0..15
        const int p = t & 15;               // 0..15
        float acc = 0.f;
        #pragma unroll
        for (int i = 0; i < DD / 4; i++) {
            float4 ev = *reinterpret_cast<const float4*>(&es[c * 132 + i * 4]);
            float4 wv = *reinterpret_cast<const float4*>(&ws[p * 132 + i * 4]);
            acc += ev.x * wv.x + ev.y * wv.y + ev.z * wv.z + ev.w * wv.w;
        }
        cbs[t] = acc + __ldg(&bias[p]);
    }
    __syncthreads();

    // ---- Phase 2: expand over channels, mask, store ---------------------
    {
        const int w = t >> 5;               // warp 0..7
        const int l = t & 31;               // lane == n within tile

        float4 xv[4];                       // xW[l][pr*4 .. pr*4+3] for pr = 0..3
        #pragma unroll
        for (int j = 0; j < 4; j++)
            xv[j] = *reinterpret_cast<const float4*>(&xw[l * 20 + j * 4]);

        #pragma unroll
        for (int k = 0; k < 8; k++) {
            int q  = w + 8 * k;             // 0..63 pair id
            int c  = q >> 2;                // channel
            int pr = q & 3;                 // patch row
            float m = ms[c];
            float4 cb4 = *reinterpret_cast<const float4*>(&cbs[c * PPV + pr * 4]);
            float4 o;
            o.x = (xv[pr].x + cb4.x) * m;
            o.y = (xv[pr].y + cb4.y) * m;
            o.z = (xv[pr].z + cb4.z) * m;
            o.w = (xv[pr].w + cb4.w) * m;
            // out[b, c, hg*4+pr, l*4 + 0..3]
            size_t off = ((size_t)((b * CO + c) * (HG * 4) + hg * 4 + pr)) * (HG * 4)
                         + (size_t)l * 4;
            *reinterpret_cast<float4*>(out + off) = o;
        }
    }
}

// ---------------------------------------------------------------------------
extern "C" void kernel_launch(void* const* d_in, const int* in_sizes, int n_in,
                              void* d_out, int out_size) {
    const float* x    = (const float*)d_in[0];   // (32, 1024, 128)
    const float* mask = (const float*)d_in[1];   // (32, 16)
    const float* emb  = (const float*)d_in[2];   // (256, 128)
    const float* W    = (const float*)d_in[3];   // (16, 128)
    const float* bias = (const float*)d_in[4];   // (16,)
    float* out = (float*)d_out;                  // (32, 16, 128, 128)

    dim3 grid(HG, NB);                           // 32 x 32 = 1024 blocks
    decoder_kernel<<<grid, 256>>>(x, W, emb, bias, mask, out);
}